// round 2
// baseline (speedup 1.0000x reference)
#include <cuda_runtime.h>
#include <cuda_bf16.h>
#include <cstddef>

// LIF recurrence: v = alpha*v + beta*c; s = (v >= 1); v = s ? 0 : v
// T sequential steps, N independent neurons. One thread per neuron.
// Output layout: out[0 : T*N] = spikes, out[T*N : 2*T*N] = voltages.

#define T_STEPS 2048
#define N_NEUR  32768
#define UNROLL  16
#define BLOCK   128

// alpha = float(exp(-1/20)) computed in double then cast (matches reference)
// beta  = float(1.0 - exp(-1/20)) likewise
__device__ __forceinline__ void lif_step(float& v, float c, float& s_out, float& v_out) {
    const float alpha = (float)0.951229424500714;     // exp(-0.05) in double -> f32
    const float beta  = (float)0.048770575499286;     // (1 - exp(-0.05)) in double -> f32
    v = alpha * v + beta * c;          // nvcc contracts to FFMA
    const bool fire = (v >= 1.0f);
    s_out = fire ? 1.0f : 0.0f;
    v = fire ? 0.0f : v;               // V_RESET = 0
    v_out = v;
}

__global__ void __launch_bounds__(BLOCK, 8)
lif_kernel(const float* __restrict__ cur,
           const float* __restrict__ v0,
           float* __restrict__ out)
{
    const int n = blockIdx.x * BLOCK + threadIdx.x;   // neuron id, 0..N-1

    float v = v0[n];

    const float* cp = cur + n;
    float* sp = out + n;                                       // spikes base
    float* vp = out + n + (size_t)T_STEPS * (size_t)N_NEUR;    // voltages base

    float bufA[UNROLL];
    float bufB[UNROLL];

    // Prologue: fill buffer A with steps [0, UNROLL)
    #pragma unroll
    for (int u = 0; u < UNROLL; ++u)
        bufA[u] = __ldcs(cp + (size_t)u * N_NEUR);

    // Main loop: 2*UNROLL steps per iteration, double-buffered so ~UNROLL
    // independent LDGs are always in flight while computing the other half.
    for (int t = 0; t < T_STEPS; t += 2 * UNROLL) {
        // Issue loads for chunk B: steps [t+UNROLL, t+2*UNROLL)
        #pragma unroll
        for (int u = 0; u < UNROLL; ++u)
            bufB[u] = __ldcs(cp + (size_t)(t + UNROLL + u) * N_NEUR);

        // Compute + store chunk A: steps [t, t+UNROLL)
        #pragma unroll
        for (int u = 0; u < UNROLL; ++u) {
            float s, vo;
            lif_step(v, bufA[u], s, vo);
            const size_t off = (size_t)(t + u) * N_NEUR;
            __stcs(sp + off, s);
            __stcs(vp + off, vo);
        }

        // Issue loads for next chunk A: steps [t+2*UNROLL, t+3*UNROLL)
        if (t + 2 * UNROLL < T_STEPS) {
            #pragma unroll
            for (int u = 0; u < UNROLL; ++u)
                bufA[u] = __ldcs(cp + (size_t)(t + 2 * UNROLL + u) * N_NEUR);
        }

        // Compute + store chunk B: steps [t+UNROLL, t+2*UNROLL)
        #pragma unroll
        for (int u = 0; u < UNROLL; ++u) {
            float s, vo;
            lif_step(v, bufB[u], s, vo);
            const size_t off = (size_t)(t + UNROLL + u) * N_NEUR;
            __stcs(sp + off, s);
            __stcs(vp + off, vo);
        }
    }
}

extern "C" void kernel_launch(void* const* d_in, const int* in_sizes, int n_in,
                              void* d_out, int out_size)
{
    const float* currents = (const float*)d_in[0];   // (T, N) fp32
    const float* v0       = (const float*)d_in[1];   // (N,)  fp32
    float* out            = (float*)d_out;           // 2*T*N fp32: [spikes; voltages]

    (void)in_sizes; (void)n_in; (void)out_size;

    lif_kernel<<<N_NEUR / BLOCK, BLOCK>>>(currents, v0, out);
}

// round 3
// speedup vs baseline: 1.0958x; 1.0958x over previous
#include <cuda_runtime.h>
#include <cuda_bf16.h>
#include <cstddef>

// LIF recurrence: v = alpha*v + beta*c; s = (v >= 1); v = s ? 0 : v
// T sequential steps, N independent neurons.
// float2 vectorization: one thread owns 2 adjacent neurons -> LDG.64/STG.64,
// halving LSU issue cost and doubling bytes-in-flight per outstanding load.
// Output layout: out[0 : T*N] = spikes, out[T*N : 2*T*N] = voltages.

#define T_STEPS 2048
#define N_NEUR  32768
#define N2      (N_NEUR / 2)          // float2 elements per step = 16384
#define UNROLL  16
#define BLOCK   64                     // 16384/64 = 256 blocks >= 148 SMs

__device__ __forceinline__ void lif_step2(float2& v, float2 c, float2& s_out, float2& v_out) {
    const float alpha = (float)0.951229424500714;   // exp(-0.05), double -> f32
    const float beta  = (float)0.048770575499286;   // 1 - exp(-0.05), double -> f32
    v.x = alpha * v.x + beta * c.x;                 // FFMA
    v.y = alpha * v.y + beta * c.y;
    const bool fx = (v.x >= 1.0f);
    const bool fy = (v.y >= 1.0f);
    s_out.x = fx ? 1.0f : 0.0f;
    s_out.y = fy ? 1.0f : 0.0f;
    v.x = fx ? 0.0f : v.x;                          // V_RESET = 0
    v.y = fy ? 0.0f : v.y;
    v_out = v;
}

__global__ void __launch_bounds__(BLOCK, 4)
lif_kernel(const float2* __restrict__ cur,
           const float2* __restrict__ v0,
           float2* __restrict__ out)
{
    const int n = blockIdx.x * BLOCK + threadIdx.x;   // float2 lane, 0..N2-1

    float2 v = v0[n];

    const float2* cp = cur + n;
    float2* sp = out + n;                             // spikes base (float2 view)
    float2* vp = out + n + (size_t)T_STEPS * (size_t)N2;  // voltages base

    float2 bufA[UNROLL];
    float2 bufB[UNROLL];

    // Prologue: fill buffer A with steps [0, UNROLL)
    #pragma unroll
    for (int u = 0; u < UNROLL; ++u)
        bufA[u] = __ldcs(cp + (size_t)u * N2);

    // 2*UNROLL steps per iteration, double-buffered: while computing/storing
    // one chunk, the other chunk's UNROLL independent LDG.64s are in flight.
    for (int t = 0; t < T_STEPS; t += 2 * UNROLL) {
        // Issue loads for chunk B: steps [t+UNROLL, t+2*UNROLL)
        #pragma unroll
        for (int u = 0; u < UNROLL; ++u)
            bufB[u] = __ldcs(cp + (size_t)(t + UNROLL + u) * N2);

        // Compute + store chunk A
        #pragma unroll
        for (int u = 0; u < UNROLL; ++u) {
            float2 s, vo;
            lif_step2(v, bufA[u], s, vo);
            const size_t off = (size_t)(t + u) * N2;
            __stcs(sp + off, s);
            __stcs(vp + off, vo);
        }

        // Issue loads for next chunk A: steps [t+2*UNROLL, t+3*UNROLL)
        if (t + 2 * UNROLL < T_STEPS) {
            #pragma unroll
            for (int u = 0; u < UNROLL; ++u)
                bufA[u] = __ldcs(cp + (size_t)(t + 2 * UNROLL + u) * N2);
        }

        // Compute + store chunk B
        #pragma unroll
        for (int u = 0; u < UNROLL; ++u) {
            float2 s, vo;
            lif_step2(v, bufB[u], s, vo);
            const size_t off = (size_t)(t + UNROLL + u) * N2;
            __stcs(sp + off, s);
            __stcs(vp + off, vo);
        }
    }
}

extern "C" void kernel_launch(void* const* d_in, const int* in_sizes, int n_in,
                              void* d_out, int out_size)
{
    const float2* currents = (const float2*)d_in[0];   // (T, N) fp32 viewed as float2
    const float2* v0       = (const float2*)d_in[1];   // (N,) fp32 viewed as float2
    float2* out            = (float2*)d_out;           // 2*T*N fp32: [spikes; voltages]

    (void)in_sizes; (void)n_in; (void)out_size;

    lif_kernel<<<N2 / BLOCK, BLOCK>>>(currents, v0, out);
}

// round 5
// speedup vs baseline: 1.1780x; 1.0750x over previous
#include <cuda_runtime.h>
#include <cuda_bf16.h>
#include <cstddef>

// LIF recurrence: v = alpha*v + beta*c; s = (v >= 1); v = s ? 0 : v
// T sequential steps, N independent neurons. One thread per 2 neurons (float2).
// Deep software pipeline: 32 LDG.64s in flight per thread (double-buffered
// 32-step chunks) -> ~28 KB/SM in flight to cover DRAM latency.
// Output layout: out[0 : T*N] = spikes, out[T*N : 2*T*N] = voltages.

#define T_STEPS 2048
#define N_NEUR  32768
#define N2      (N_NEUR / 2)          // float2 elements per step = 16384
#define UNROLL  32
#define BLOCK   64                     // 16384/64 = 256 blocks >= 148 SMs

__device__ __forceinline__ void lif_step2(float2& v, float2 c, float2& s_out, float2& v_out) {
    const float alpha = (float)0.951229424500714;   // exp(-0.05), double -> f32
    const float beta  = (float)0.048770575499286;   // 1 - exp(-0.05), double -> f32
    v.x = alpha * v.x + beta * c.x;                 // FFMA
    v.y = alpha * v.y + beta * c.y;
    const bool fx = (v.x >= 1.0f);
    const bool fy = (v.y >= 1.0f);
    s_out.x = fx ? 1.0f : 0.0f;
    s_out.y = fy ? 1.0f : 0.0f;
    v.x = fx ? 0.0f : v.x;                          // V_RESET = 0
    v.y = fy ? 0.0f : v.y;
    v_out = v;
}

__global__ void __launch_bounds__(BLOCK, 4)
lif_kernel(const float2* __restrict__ cur,
           const float2* __restrict__ v0,
           float2* __restrict__ out)
{
    const int n = blockIdx.x * BLOCK + threadIdx.x;   // float2 lane, 0..N2-1

    float2 v = v0[n];

    const float2* cp = cur + n;
    float2* sp = out + n;                                  // spikes base
    float2* vp = out + n + (size_t)T_STEPS * (size_t)N2;   // voltages base

    float2 bufA[UNROLL];
    float2 bufB[UNROLL];

    // Prologue: fill buffer A with steps [0, UNROLL)
    #pragma unroll
    for (int u = 0; u < UNROLL; ++u)
        bufA[u] = __ldcs(cp + (size_t)u * N2);

    // 2*UNROLL steps per iteration, double-buffered: while computing/storing
    // one chunk, the other chunk's UNROLL independent LDG.64s are in flight.
    for (int t = 0; t < T_STEPS; t += 2 * UNROLL) {
        // Issue loads for chunk B: steps [t+UNROLL, t+2*UNROLL)
        #pragma unroll
        for (int u = 0; u < UNROLL; ++u)
            bufB[u] = __ldcs(cp + (size_t)(t + UNROLL + u) * N2);

        // Compute + store chunk A
        #pragma unroll
        for (int u = 0; u < UNROLL; ++u) {
            float2 s, vo;
            lif_step2(v, bufA[u], s, vo);
            const size_t off = (size_t)(t + u) * N2;
            __stcs(sp + off, s);
            __stcs(vp + off, vo);
        }

        // Issue loads for next chunk A: steps [t+2*UNROLL, t+3*UNROLL)
        if (t + 2 * UNROLL < T_STEPS) {
            #pragma unroll
            for (int u = 0; u < UNROLL; ++u)
                bufA[u] = __ldcs(cp + (size_t)(t + 2 * UNROLL + u) * N2);
        }

        // Compute + store chunk B
        #pragma unroll
        for (int u = 0; u < UNROLL; ++u) {
            float2 s, vo;
            lif_step2(v, bufB[u], s, vo);
            const size_t off = (size_t)(t + UNROLL + u) * N2;
            __stcs(sp + off, s);
            __stcs(vp + off, vo);
        }
    }
}

extern "C" void kernel_launch(void* const* d_in, const int* in_sizes, int n_in,
                              void* d_out, int out_size)
{
    const float2* currents = (const float2*)d_in[0];   // (T, N) fp32 as float2
    const float2* v0       = (const float2*)d_in[1];   // (N,) fp32 as float2
    float2* out            = (float2*)d_out;           // 2*T*N fp32: [spikes; voltages]

    (void)in_sizes; (void)n_in; (void)out_size;

    lif_kernel<<<N2 / BLOCK, BLOCK>>>(currents, v0, out);
}